// round 15
// baseline (speedup 1.0000x reference)
#include <cuda_runtime.h>
#include <cuda_fp16.h>
#include <cstdint>

// ============================ problem sizes ============================
#define BB    32
#define CIN   256
#define COUT  512
#define HWSZ  4096                  // 64*64
#define KTOT  256
#define NPIX  131072.0f             // B*H*W per channel

// ============================ device scratch ============================
__device__ __align__(128) __half g_w[COUT * KTOT];              // 256 KB [o][c]
__device__ __align__(128) __half g_a[(size_t)131072 * KTOT];    // 67 MB  [mtile][k][128m]
__device__ __align__(128) float  g_C[CIN * CIN];                // 256 KB  A^T A
__device__ float  g_S[CIN];                                     // column sums of A
__device__ float  g_ssq[COUT];                                  // w_o^T C w_o partials
__device__ float2 g_gabe[COUT];                                 // (gamma*inv, beta-mean*ga)

// ============================ helpers ============================
__device__ __forceinline__ uint32_t smem_u32(const void* p) {
    uint32_t a;
    asm("{ .reg .u64 t; cvta.to.shared.u64 t, %1; cvt.u32.u64 %0, t; }" : "=r"(a) : "l"(p));
    return a;
}
__device__ __forceinline__ void ldsm_x4(uint32_t& r0, uint32_t& r1, uint32_t& r2, uint32_t& r3,
                                        uint32_t addr) {
    asm volatile("ldmatrix.sync.aligned.m8n8.x4.shared.b16 {%0,%1,%2,%3}, [%4];"
                 : "=r"(r0), "=r"(r1), "=r"(r2), "=r"(r3) : "r"(addr));
}
__device__ __forceinline__ void ldsm_x4_t(uint32_t& r0, uint32_t& r1, uint32_t& r2, uint32_t& r3,
                                          uint32_t addr) {
    asm volatile("ldmatrix.sync.aligned.m8n8.x4.trans.shared.b16 {%0,%1,%2,%3}, [%4];"
                 : "=r"(r0), "=r"(r1), "=r"(r2), "=r"(r3) : "r"(addr));
}
__device__ __forceinline__ void mma16816(float* d, const uint32_t* a, uint32_t b0, uint32_t b1) {
    asm volatile("mma.sync.aligned.m16n8k16.row.col.f32.f16.f16.f32 "
                 "{%0,%1,%2,%3}, {%4,%5,%6,%7}, {%8,%9}, {%0,%1,%2,%3};"
                 : "+f"(d[0]), "+f"(d[1]), "+f"(d[2]), "+f"(d[3])
                 : "r"(a[0]), "r"(a[1]), "r"(a[2]), "r"(a[3]), "r"(b0), "r"(b1));
}
__device__ __forceinline__ void cp_async16(uint32_t smem_dst, const void* gsrc) {
    asm volatile("cp.async.cg.shared.global [%0], [%1], 16;"
                 :: "r"(smem_dst), "l"(gsrc) : "memory");
}
#define CP_COMMIT() asm volatile("cp.async.commit_group;" ::: "memory")
#define CP_WAIT0()  asm volatile("cp.async.wait_group 0;" ::: "memory")
#define CP_WAIT1()  asm volatile("cp.async.wait_group 1;" ::: "memory")

// LCG jump tables: s -> 65539*s + 1 (mod 2^32)
struct LCGTab { unsigned A[21]; unsigned C[21]; };
__host__ __device__ constexpr LCGTab make_tab() {
    LCGTab t{};
    unsigned a = 65539u, c = 1u;
    for (int j = 0; j < 21; j++) {
        t.A[j] = a; t.C[j] = c;
        unsigned c2 = a * c + c;
        a = a * a; c = c2;
    }
    return t;
}

// ============================ kernel 0: init (W + zero accumulators) ============================
__global__ void k_init(const float* __restrict__ w) {
    int i = blockIdx.x * blockDim.x + threadIdx.x;   // 0 .. 131071
    g_w[i] = __float2half_rn(w[i]);
    if (i < CIN * CIN) g_C[i] = 0.0f;
    if (i < CIN)       g_S[i] = 0.0f;
    if (i < COUT)      g_ssq[i] = 0.0f;
}

// ============================ kernel 1: prep A = relu(x+noise) fp16 (noise fused) ============================
// Layout g_a[mtile][k][128 m]. Block = one channel c, 1024 m. Also accumulates S[c].
__global__ void __launch_bounds__(256) k_prep(const float* __restrict__ x) {
    constexpr LCGTab T = make_tab();
    __shared__ float red[8];
    int tid = threadIdx.x, warp = tid >> 5, lane = tid & 31;
    int c = blockIdx.x >> 7;
    int m = ((blockIdx.x & 127) << 10) + tid * 4;
    int batch = m >> 12, hw = m & 4095;

    // noise for elements i0..i0+3, i0 = c*HWSZ + hw (batch-independent broadcast)
    unsigned n = (unsigned)(c * HWSZ + hw) + 1u;
    unsigned rA = 1u, rC = 0u;
    #pragma unroll
    for (int j = 0; j < 21; j++) {
        if ((n >> j) & 1u) { rA = T.A[j] * rA; rC = T.A[j] * rC + T.C[j]; }
    }
    unsigned s1 = rA * 12345u + rC;
    unsigned s2 = 65539u * s1 + 1u;
    unsigned s3 = 65539u * s2 + 1u;
    unsigned s4 = 65539u * s3 + 1u;
    const float sc = (float)(0.1 / 4294967295.0);

    float4 xv = *(const float4*)(x + ((size_t)(batch * CIN + c)) * HWSZ + hw);
    float v0 = fmaxf(xv.x + (float)s1 * sc, 0.0f);
    float v1 = fmaxf(xv.y + (float)s2 * sc, 0.0f);
    float v2 = fmaxf(xv.z + (float)s3 * sc, 0.0f);
    float v3 = fmaxf(xv.w + (float)s4 * sc, 0.0f);

    __half2 h01 = __floats2half2_rn(v0, v1);
    __half2 h23 = __floats2half2_rn(v2, v3);
    uint2 pack;
    pack.x = *(uint32_t*)&h01;
    pack.y = *(uint32_t*)&h23;
    int mtile = m >> 7, mloc = m & 127;
    *(uint2*)(g_a + (size_t)mtile * 32768 + c * 128 + mloc) = pack;

    float s = (v0 + v1) + (v2 + v3);
    #pragma unroll
    for (int off = 16; off; off >>= 1) s += __shfl_xor_sync(0xFFFFFFFFu, s, off);
    if (lane == 0) red[warp] = s;
    __syncthreads();
    if (tid == 0) {
        float tot = 0.0f;
        #pragma unroll
        for (int i = 0; i < 8; i++) tot += red[i];
        atomicAdd(&g_S[c], tot);
    }
}

// ============================ kernel 2: stats C = A^T A (symmetric: 3 tiles) ============================
// grid (3, 128): bx 0->(0,0) 1->(1,1) 2->(0,1); by -> 1024-m chunk (16 slabs of 64 m).
#define ST_STRIDE 72
#define ST_BUF_B  36864                    // 256 rows * 144 B
#define ST_TOTAL  73728

__global__ void __launch_bounds__(256, 2) k_stats() {
    extern __shared__ char smem[];
    uint32_t sb_u = smem_u32(smem);

    int tid = threadIdx.x, warp = tid >> 5, lane = tid & 31;
    int ti = (blockIdx.x == 1) ? 1 : 0;
    int tj = (blockIdx.x == 0) ? 0 : 1;
    bool diag = (ti == tj);
    int rows = diag ? 128 : 256;
    int chunk = blockIdx.y;                // 0..127, 8 mtiles each

    int mw = (warp >> 2) * 64;
    int nw = (warp & 3) * 32;
    int g = lane >> 2, t = lane & 3;

    float acc[16][4];
    #pragma unroll
    for (int i = 0; i < 16; i++)
        #pragma unroll
        for (int j = 0; j < 4; j++) acc[i][j] = 0.0f;

    uint32_t aoff = (uint32_t)((mw + (lane & 15)) * ST_STRIDE + (lane >> 4) * 8) * 2u;
    uint32_t boff_frag = (uint32_t)((nw + (lane & 7) + ((lane >> 4) << 3)) * ST_STRIDE
                                    + ((lane >> 3) & 1) * 8) * 2u;

    auto issue = [&](int sb, int buf) {
        int mtile = chunk * 8 + (sb >> 1);
        int m0 = (sb & 1) * 64;
        uint32_t dstb = sb_u + (uint32_t)buf * ST_BUF_B;
        const __half* srcb = g_a + (size_t)mtile * 32768 + m0;
        for (int u = tid; u < rows * 8; u += 256) {
            int r = u >> 3, part = u & 7;
            int krow = (r < 128) ? ti * 128 + r : tj * 128 + (r - 128);
            cp_async16(dstb + (uint32_t)(r * 144 + part * 16),
                       srcb + (size_t)krow * 128 + part * 8);
        }
        CP_COMMIT();
    };

    issue(0, 0);
    for (int sb = 0; sb < 16; sb++) {
        if (sb + 1 < 16) { issue(sb + 1, (sb + 1) & 1); CP_WAIT1(); }
        else             { CP_WAIT0(); }
        __syncthreads();

        uint32_t bufb = sb_u + (uint32_t)((sb & 1) * ST_BUF_B);
        uint32_t aaddr = bufb + aoff;
        uint32_t bbase = bufb + (diag ? 0u : (uint32_t)(128 * 144)) + boff_frag;
        #pragma unroll
        for (int ks = 0; ks < 4; ks++) {
            uint32_t afr[4][4];
            #pragma unroll
            for (int mi = 0; mi < 4; mi++)
                ldsm_x4(afr[mi][0], afr[mi][1], afr[mi][2], afr[mi][3],
                        aaddr + (uint32_t)(mi * 16 * ST_STRIDE + ks * 16) * 2u);
            uint32_t bfr[2][4];
            #pragma unroll
            for (int nip = 0; nip < 2; nip++)
                ldsm_x4(bfr[nip][0], bfr[nip][1], bfr[nip][2], bfr[nip][3],
                        bbase + (uint32_t)(nip * 16 * ST_STRIDE + ks * 16) * 2u);
            #pragma unroll
            for (int mi = 0; mi < 4; mi++)
                #pragma unroll
                for (int ni = 0; ni < 4; ni++)
                    mma16816(acc[mi * 4 + ni], afr[mi],
                             bfr[ni >> 1][(ni & 1) * 2], bfr[ni >> 1][(ni & 1) * 2 + 1]);
        }
        __syncthreads();
    }

    #pragma unroll
    for (int mi = 0; mi < 4; mi++)
        #pragma unroll
        for (int ni = 0; ni < 4; ni++) {
            int ci = ti * 128 + mw + mi * 16 + g;
            int cj = tj * 128 + nw + ni * 8 + t * 2;
            atomicAdd(&g_C[ci * CIN + cj],           acc[mi * 4 + ni][0]);
            atomicAdd(&g_C[ci * CIN + cj + 1],       acc[mi * 4 + ni][1]);
            atomicAdd(&g_C[(ci + 8) * CIN + cj],     acc[mi * 4 + ni][2]);
            atomicAdd(&g_C[(ci + 8) * CIN + cj + 1], acc[mi * 4 + ni][3]);
        }
}

// ============================ kernel 2b: mirror C upper -> lower ============================
__global__ void k_mirr() {
    int idx = blockIdx.x * 256 + threadIdx.x;     // 0..16383
    int r = idx >> 7, c2 = idx & 127;
    g_C[(128 + c2) * CIN + r] = g_C[r * CIN + 128 + c2];
}

// ============================ kernel 3: ssq partials (bilinear r-split) ============================
__global__ void __launch_bounds__(256) k_fin(void) {
    __shared__ float smw[4][64];
    __shared__ float sred[8][4];
    int tid = threadIdx.x, warp = tid >> 5, lane = tid & 31;
    int o0 = blockIdx.x * 4;
    int r0 = blockIdx.y * 64;

    {
        int q = tid >> 6, j = tid & 63;
        smw[q][j] = __half2float(g_w[(size_t)(o0 + q) * KTOT + r0 + j]);
    }
    __syncthreads();

    float wv[4];
    #pragma unroll
    for (int q = 0; q < 4; q++) wv[q] = __half2float(g_w[(size_t)(o0 + q) * KTOT + tid]);

    float u[4] = {0.0f, 0.0f, 0.0f, 0.0f};
    #pragma unroll 8
    for (int j = 0; j < 64; j++) {
        float cr = g_C[(r0 + j) * CIN + tid];
        #pragma unroll
        for (int q = 0; q < 4; q++) u[q] += smw[q][j] * cr;
    }
    float p[4];
    #pragma unroll
    for (int q = 0; q < 4; q++) {
        p[q] = u[q] * wv[q];
        #pragma unroll
        for (int off = 16; off; off >>= 1) p[q] += __shfl_xor_sync(0xFFFFFFFFu, p[q], off);
    }
    if (lane == 0) {
        #pragma unroll
        for (int q = 0; q < 4; q++) sred[warp][q] = p[q];
    }
    __syncthreads();
    if (tid < 4) {
        float tot = 0.0f;
        #pragma unroll
        for (int w2 = 0; w2 < 8; w2++) tot += sred[w2][tid];
        atomicAdd(&g_ssq[o0 + tid], tot);
    }
}

// ============================ kernel 3b: finalize gabe ============================
__global__ void k_fin2(const float* __restrict__ gamma, const float* __restrict__ beta) {
    __shared__ float sS[256];
    int tid = threadIdx.x;
    if (tid < 256) sS[tid] = g_S[tid];
    __syncthreads();
    int o = blockIdx.x * 256 + tid;
    float mean = 0.0f;
    #pragma unroll 8
    for (int c = 0; c < 256; c++)
        mean += __half2float(g_w[(size_t)o * KTOT + c]) * sS[c];
    mean *= (1.0f / NPIX);
    float ey2 = g_ssq[o] * (1.0f / NPIX);
    float var = ey2 - mean * mean;
    float inv = rsqrtf(var + 1e-5f);
    float ga = gamma[o] * inv;
    float be = beta[o] - mean * ga;
    g_gabe[o] = make_float2(ga, be);
}

// ============================ kernel 4: GEMM + fused normalize -> out ============================
// A prefab fp16, full-K resident via cp.async burst. B staged as 128n x 128k half-tiles
// (2 phases per nt; FIX: 8 uint4 per thread = full 32KB tile). Per-warp transpose epilogue.
#define SMA_OFF    0                       // [256 k][136 m] half = 69632 B
#define SMB_OFF    69632                   // [128 n][136 k] half = 34816 B
#define SM_TOTAL   104448
#define SMA_STRIDE 136
#define SMB_STRIDE 136

__global__ void __launch_bounds__(256, 2) k_gemm(float* __restrict__ out) {
    extern __shared__ char smem[];
    __half* smB = (__half*)(smem + SMB_OFF);
    uint32_t smA_u = smem_u32(smem);
    uint32_t smB_u = smem_u32(smB);

    int tid = threadIdx.x, warp = tid >> 5, lane = tid & 31;
    int mtile = blockIdx.x;            // 0..1023
    int b   = mtile >> 5;
    int hw0 = (mtile & 31) << 7;

    int mw = (warp >> 2) * 64;
    int nw = (warp & 3) * 32;
    int g = lane >> 2, t = lane & 3;

    // prologue: cp.async full A tile (256 rows x 128 m fp16 = 256 B/row -> 16 parts)
    {
        const __half* srcb = g_a + (size_t)mtile * 32768;
        #pragma unroll
        for (int it = 0; it < 16; it++) {
            int u = it * 256 + tid;
            int r = u >> 4, part = u & 15;
            cp_async16(smA_u + (uint32_t)(r * 272 + part * 16),
                       srcb + (size_t)r * 128 + part * 8);
        }
        CP_COMMIT();
    }

    float acc[16][4];
    #pragma unroll
    for (int i = 0; i < 16; i++)
        #pragma unroll
        for (int j = 0; j < 4; j++) acc[i][j] = 0.0f;

    uint32_t aaddr = smA_u + (uint32_t)(((lane & 7) + ((lane >> 4) << 3)) * SMA_STRIDE
                                        + mw + ((lane >> 3) & 1) * 8) * 2u;
    uint32_t blane = smB_u + (uint32_t)((nw + (lane & 7) + ((lane >> 4) << 3)) * SMB_STRIDE
                                        + ((lane >> 3) & 1) * 8) * 2u;

    for (int nt = 0; nt < 4; nt++) {
        for (int kc2 = 0; kc2 < 2; kc2++) {
            {   // B half-tile (nt, kc2): 128 n-rows x 128 k halves = 32KB
                // 2 threads/row, 64 halves (8 uint4) each  [R14 fix]
                int r = tid >> 1, seg = tid & 1;
                const uint4* src = (const uint4*)(g_w + (size_t)(nt * 128 + r) * KTOT
                                                  + kc2 * 128 + seg * 64);
                uint4* dst = (uint4*)(smB + r * SMB_STRIDE + seg * 64);
                #pragma unroll
                for (int i = 0; i < 8; i++) dst[i] = src[i];
            }
            if (nt == 0 && kc2 == 0) CP_WAIT0();      // A tile resident
            __syncthreads();

            #pragma unroll
            for (int ks = 0; ks < 8; ks++) {
                uint32_t afr[4][4];
                #pragma unroll
                for (int mi = 0; mi < 4; mi++)
                    ldsm_x4_t(afr[mi][0], afr[mi][1], afr[mi][2], afr[mi][3],
                              aaddr + (uint32_t)((kc2 * 128 + ks * 16) * SMA_STRIDE) * 2u
                                    + (uint32_t)(mi * 16) * 2u);
                uint32_t bfr[2][4];
                #pragma unroll
                for (int nip = 0; nip < 2; nip++)
                    ldsm_x4(bfr[nip][0], bfr[nip][1], bfr[nip][2], bfr[nip][3],
                            blane + (uint32_t)(nip * 16 * SMB_STRIDE + ks * 16) * 2u);
                #pragma unroll
                for (int mi = 0; mi < 4; mi++)
                    #pragma unroll
                    for (int ni = 0; ni < 4; ni++)
                        mma16816(acc[mi * 4 + ni], afr[mi],
                                 bfr[ni >> 1][(ni & 1) * 2], bfr[ni >> 1][(ni & 1) * 2 + 1]);
            }
            __syncthreads();
        }

        // ---- epilogue: per-warp transpose + normalize + coalesced fp32 stores ----
        float2 gb[8];
        #pragma unroll
        for (int ni = 0; ni < 4; ni++) {
            int n = nt * 128 + nw + ni * 8 + t * 2;
            gb[ni * 2]     = g_gabe[n];
            gb[ni * 2 + 1] = g_gabe[n + 1];
        }
        float* smW = (float*)(smem + SMB_OFF) + warp * 544;   // 8n x 68m floats
        #pragma unroll
        for (int ni = 0; ni < 4; ni++) {
            float2 q0 = gb[ni * 2], q1 = gb[ni * 2 + 1];
            #pragma unroll
            for (int mi = 0; mi < 4; mi++) {
                int mloc = mi * 16 + g;
                smW[(t * 2) * 68 + mloc]         = acc[mi * 4 + ni][0] * q0.x + q0.y;
                smW[(t * 2 + 1) * 68 + mloc]     = acc[mi * 4 + ni][1] * q1.x + q1.y;
                smW[(t * 2) * 68 + mloc + 8]     = acc[mi * 4 + ni][2] * q0.x + q0.y;
                smW[(t * 2 + 1) * 68 + mloc + 8] = acc[mi * 4 + ni][3] * q1.x + q1.y;
                acc[mi * 4 + ni][0] = 0.0f; acc[mi * 4 + ni][1] = 0.0f;
                acc[mi * 4 + ni][2] = 0.0f; acc[mi * 4 + ni][3] = 0.0f;
            }
            __syncwarp();
            #pragma unroll
            for (int it = 0; it < 4; it++) {
                int u = it * 32 + lane;
                int r = u >> 4, part = u & 15;
                float4 v = *(float4*)(smW + r * 68 + part * 4);
                __stcs((float4*)(out + ((size_t)(b * COUT + nt * 128 + nw + ni * 8 + r)) * HWSZ
                                 + hw0 + mw + part * 4), v);
            }
            __syncwarp();
        }
        __syncthreads();                 // all warps done with smB region before next B staging
    }
}

// ============================ launcher ============================
extern "C" void kernel_launch(void* const* d_in, const int* in_sizes, int n_in,
                              void* d_out, int out_size) {
    const float* x     = (const float*)d_in[0];
    const float* w     = (const float*)d_in[1];
    // d_in[2] = conv_b: exactly cancelled by BatchNorm mean subtraction.
    const float* gamma = (const float*)d_in[3];
    const float* beta  = (const float*)d_in[4];
    float* out = (float*)d_out;

    cudaFuncSetAttribute(k_stats, cudaFuncAttributeMaxDynamicSharedMemorySize, ST_TOTAL);
    cudaFuncSetAttribute(k_gemm,  cudaFuncAttributeMaxDynamicSharedMemorySize, SM_TOTAL);

    k_init<<<512, 256>>>(w);                       // fp16 W + zero C/S/ssq
    k_prep<<<32768, 256>>>(x);                     // A = relu(x+noise) fp16 tiles + S (noise fused)
    k_stats<<<dim3(3, 128), 256, ST_TOTAL>>>();    // C upper (symmetry: 3 of 4 tiles)
    k_mirr<<<64, 256>>>();                         // mirror C upper -> lower
    k_fin<<<dim3(128, 4), 256>>>();                // ssq partials (r-split bilinear)
    k_fin2<<<2, 256>>>(gamma, beta);               // mean + (ga, be)
    k_gemm<<<1024, 256, SM_TOTAL>>>(out);          // y -> normalize -> out (per-warp epi)
}

// round 16
// speedup vs baseline: 1.0521x; 1.0521x over previous
#include <cuda_runtime.h>
#include <cuda_fp16.h>
#include <cstdint>

// ============================ problem sizes ============================
#define BB    32
#define CIN   256
#define COUT  512
#define HWSZ  4096                  // 64*64
#define KTOT  256
#define NPIX  131072.0f             // B*H*W per channel

// ============================ device scratch ============================
__device__ __align__(128) float  g_noise[CIN * HWSZ];            // 4 MB
__device__ __align__(128) __half g_w[COUT * KTOT];               // 256 KB  [o][c]
__device__ __align__(128) __half g_y[(size_t)BB * COUT * HWSZ];  // 134 MB
__device__ float g_sum[COUT];
__device__ float g_sq[COUT];

// ============================ helpers ============================
__device__ __forceinline__ uint32_t smem_u32(const void* p) {
    uint32_t a;
    asm("{ .reg .u64 t; cvta.to.shared.u64 t, %1; cvt.u32.u64 %0, t; }" : "=r"(a) : "l"(p));
    return a;
}
__device__ __forceinline__ void ldsm_x4(uint32_t& r0, uint32_t& r1, uint32_t& r2, uint32_t& r3,
                                        uint32_t addr) {
    asm volatile("ldmatrix.sync.aligned.m8n8.x4.shared.b16 {%0,%1,%2,%3}, [%4];"
                 : "=r"(r0), "=r"(r1), "=r"(r2), "=r"(r3) : "r"(addr));
}
__device__ __forceinline__ void ldsm_x4_t(uint32_t& r0, uint32_t& r1, uint32_t& r2, uint32_t& r3,
                                          uint32_t addr) {
    asm volatile("ldmatrix.sync.aligned.m8n8.x4.trans.shared.b16 {%0,%1,%2,%3}, [%4];"
                 : "=r"(r0), "=r"(r1), "=r"(r2), "=r"(r3) : "r"(addr));
}
__device__ __forceinline__ void mma16816(float* d, const uint32_t* a, uint32_t b0, uint32_t b1) {
    asm volatile("mma.sync.aligned.m16n8k16.row.col.f32.f16.f16.f32 "
                 "{%0,%1,%2,%3}, {%4,%5,%6,%7}, {%8,%9}, {%0,%1,%2,%3};"
                 : "+f"(d[0]), "+f"(d[1]), "+f"(d[2]), "+f"(d[3])
                 : "r"(a[0]), "r"(a[1]), "r"(a[2]), "r"(a[3]), "r"(b0), "r"(b1));
}

// ============================ kernel 0: init ============================
struct LCGTab { unsigned A[21]; unsigned C[21]; };
__host__ __device__ constexpr LCGTab make_tab() {
    LCGTab t{};
    unsigned a = 65539u, c = 1u;
    for (int j = 0; j < 21; j++) {
        t.A[j] = a; t.C[j] = c;
        unsigned c2 = a * c + c;
        a = a * a; c = c2;
    }
    return t;
}
__global__ void k_init(const float* __restrict__ w) {
    constexpr LCGTab T = make_tab();
    int i = blockIdx.x * blockDim.x + threadIdx.x;   // 0 .. 1048575
    unsigned n = (unsigned)i + 1u;
    unsigned rA = 1u, rC = 0u;
    #pragma unroll
    for (int j = 0; j < 21; j++) {
        if ((n >> j) & 1u) { rA = T.A[j] * rA; rC = T.A[j] * rC + T.C[j]; }
    }
    unsigned seed = rA * 12345u + rC;
    g_noise[i] = (float)seed * (float)(0.1 / 4294967295.0);

    if (i < COUT * KTOT) g_w[i] = __float2half_rn(w[i]);
    if (i < COUT) { g_sum[i] = 0.0f; g_sq[i] = 0.0f; }
}

// ============================ kernel 1: fused GEMM (R8, 2 CTAs/SM) ============================
// CTA: 128 m-pixels x all 512 out-channels. A = relu(x+noise) fp16, full-K in smem
// (x read from DRAM once). B single-buffered per phase from L2. Epilogue reuses the
// smB region in two 64-n passes. smem 87KB + regs<=128 -> 2 CTAs/SM.
#define SMA_OFF    0                       // [256 k][136 m] half = 69632 B
#define SMB_OFF    69632                   // [128 n][72 k] half = 18432 B
#define STAT_OFF   88064                   // 256 floats = 1024 B
#define SM_TOTAL   89088
#define SMA_STRIDE 136
#define SMB_STRIDE 72

__global__ void __launch_bounds__(256, 2) k_gemm(const float* __restrict__ x) {
    extern __shared__ char smem[];
    __half* smA = (__half*)(smem + SMA_OFF);
    __half* smB = (__half*)(smem + SMB_OFF);
    float*  sums = (float*)(smem + STAT_OFF);
    float*  sqs  = sums + 128;
    uint32_t smA_u = smem_u32(smA);
    uint32_t smB_u = smem_u32(smB);

    int tid = threadIdx.x, warp = tid >> 5, lane = tid & 31;
    int mtile = blockIdx.x;            // 0..1023
    int b   = mtile >> 5;
    int hw0 = (mtile & 31) << 7;       // 128-pixel contiguous hw slab

    int mw = (warp >> 2) * 64;         // warp m offset
    int nw = (warp & 3) * 32;          // warp n offset within 128-n tile
    int cl = warp * 8;                 // channels staged per warp per chunk
    int brow = tid & 127, bpart = tid >> 7;

    float acc[16][4];
    #pragma unroll
    for (int i = 0; i < 16; i++)
        #pragma unroll
        for (int j = 0; j < 4; j++) acc[i][j] = 0.0f;

    uint32_t aaddr = smA_u + (uint32_t)(((lane & 7) + ((lane >> 4) << 3)) * SMA_STRIDE
                                        + mw + ((lane >> 3) & 1) * 8) * 2u;
    uint32_t blane = smB_u + (uint32_t)((nw + (lane & 7) + ((lane >> 4) << 3)) * SMB_STRIDE
                                        + ((lane >> 3) & 1) * 8) * 2u;
    int g = lane >> 2, t = lane & 3;

    for (int nt = 0; nt < 4; nt++) {
        for (int kc = 0; kc < 4; kc++) {
            // smB (and, for nt==0, smA chunk kc) are free here (sync at end of prev phase)
            if (nt == 0) {
                #pragma unroll
                for (int r = 0; r < 8; r++) {
                    int c = kc * 64 + cl + r;
                    float4 xv = *(const float4*)(x + ((size_t)(b * CIN + c)) * HWSZ + hw0 + lane * 4);
                    float4 nv = *(const float4*)(g_noise + (size_t)c * HWSZ + hw0 + lane * 4);
                    __half2 h01 = __floats2half2_rn(fmaxf(xv.x + nv.x, 0.0f), fmaxf(xv.y + nv.y, 0.0f));
                    __half2 h23 = __floats2half2_rn(fmaxf(xv.z + nv.z, 0.0f), fmaxf(xv.w + nv.w, 0.0f));
                    uint2 pack;
                    pack.x = *(uint32_t*)&h01;
                    pack.y = *(uint32_t*)&h23;
                    *(uint2*)(smA + c * SMA_STRIDE + lane * 4) = pack;
                }
            }
            {   // B tile for (nt, kc): L2-resident weights
                const uint4* src = (const uint4*)(g_w + (size_t)(nt * 128 + brow) * KTOT
                                                  + kc * 64 + bpart * 32);
                uint4* dst = (uint4*)(smB + brow * SMB_STRIDE + bpart * 32);
                dst[0] = src[0]; dst[1] = src[1]; dst[2] = src[2]; dst[3] = src[3];
            }
            __syncthreads();

            uint32_t abase = aaddr + (uint32_t)(kc * 64 * SMA_STRIDE) * 2u;
            #pragma unroll
            for (int ks = 0; ks < 4; ks++) {
                uint32_t afr[4][4];
                #pragma unroll
                for (int mi = 0; mi < 4; mi++)
                    ldsm_x4_t(afr[mi][0], afr[mi][1], afr[mi][2], afr[mi][3],
                              abase + (uint32_t)(ks * 16 * SMA_STRIDE + mi * 16) * 2u);
                uint32_t bfr[2][4];
                #pragma unroll
                for (int nip = 0; nip < 2; nip++)
                    ldsm_x4(bfr[nip][0], bfr[nip][1], bfr[nip][2], bfr[nip][3],
                            blane + (uint32_t)(nip * 16 * SMB_STRIDE + ks * 16) * 2u);
                #pragma unroll
                for (int mi = 0; mi < 4; mi++)
                    #pragma unroll
                    for (int ni = 0; ni < 4; ni++)
                        mma16816(acc[mi * 4 + ni], afr[mi],
                                 bfr[ni >> 1][(ni & 1) * 2], bfr[ni >> 1][(ni & 1) * 2 + 1]);
            }
            __syncthreads();
        }

        // ---- epilogue for ntile nt: BN stats + y fp16 in two 64-n passes via smB ----
        if (tid < 128) { sums[tid] = 0.0f; sqs[tid] = 0.0f; }

        float lsum[8], lsq[8];
        #pragma unroll
        for (int j = 0; j < 8; j++) { lsum[j] = 0.0f; lsq[j] = 0.0f; }
        #pragma unroll
        for (int mi = 0; mi < 4; mi++)
            #pragma unroll
            for (int ni = 0; ni < 4; ni++) {
                float c0 = acc[mi * 4 + ni][0], c1 = acc[mi * 4 + ni][1];
                float c2 = acc[mi * 4 + ni][2], c3 = acc[mi * 4 + ni][3];
                int j0 = ni * 2;
                lsum[j0]     += c0 + c2;  lsq[j0]     += c0 * c0 + c2 * c2;
                lsum[j0 + 1] += c1 + c3;  lsq[j0 + 1] += c1 * c1 + c3 * c3;
            }
        #pragma unroll
        for (int j = 0; j < 8; j++) {
            #pragma unroll
            for (int off = 4; off <= 16; off <<= 1) {
                lsum[j] += __shfl_xor_sync(0xFFFFFFFFu, lsum[j], off);
                lsq[j]  += __shfl_xor_sync(0xFFFFFFFFu, lsq[j], off);
            }
        }
        __syncthreads();                      // stat zeroing visible; smB free
        if (g == 0) {
            #pragma unroll
            for (int j = 0; j < 8; j++) {
                int n = nw + (j >> 1) * 8 + t * 2 + (j & 1);
                atomicAdd(&sums[n], lsum[j]);
                atomicAdd(&sqs[n],  lsq[j]);
            }
        }

        __half* smY = smB;                    // [64 n][136 m] transpose buffer
        #pragma unroll
        for (int p = 0; p < 2; p++) {
            if ((warp & 2) == p * 2) {        // warps owning n in [64p, 64p+64)
                int nl = nw - p * 64;         // 0 or 32
                #pragma unroll
                for (int mi = 0; mi < 4; mi++)
                    #pragma unroll
                    for (int ni = 0; ni < 4; ni++) {
                        float c0 = acc[mi * 4 + ni][0], c1 = acc[mi * 4 + ni][1];
                        float c2 = acc[mi * 4 + ni][2], c3 = acc[mi * 4 + ni][3];
                        int m0 = mw + mi * 16 + g;
                        int n0 = nl + ni * 8 + t * 2;
                        smY[n0 * SMA_STRIDE + m0]           = __float2half_rn(c0);
                        smY[(n0 + 1) * SMA_STRIDE + m0]     = __float2half_rn(c1);
                        smY[n0 * SMA_STRIDE + m0 + 8]       = __float2half_rn(c2);
                        smY[(n0 + 1) * SMA_STRIDE + m0 + 8] = __float2half_rn(c3);
                    }
            }
            __syncthreads();
            // all 8 warps store 64 rows (8 rows each), coalesced 256B per row
            #pragma unroll
            for (int i = 0; i < 8; i++) {
                int n = warp * 8 + i;
                uint2 v = *(uint2*)(smY + n * SMA_STRIDE + lane * 4);
                *(uint2*)(g_y + ((size_t)(b * COUT + nt * 128 + p * 64 + n)) * HWSZ
                          + hw0 + lane * 4) = v;
            }
            __syncthreads();
        }

        if (tid < 128) {
            atomicAdd(&g_sum[nt * 128 + tid], sums[tid]);
            atomicAdd(&g_sq[nt * 128 + tid],  sqs[tid]);
        }
        // reset acc for next ntile
        #pragma unroll
        for (int i = 0; i < 16; i++)
            #pragma unroll
            for (int j = 0; j < 4; j++) acc[i][j] = 0.0f;
    }
}

// ============================ kernel 2: BN normalize (wide) ============================
// 16 elems per thread (all same channel): 32B y read + 64B out write, MLP 2/4.
__global__ void __launch_bounds__(256) k_norm(float* __restrict__ out,
                                              const float* __restrict__ gamma,
                                              const float* __restrict__ beta) {
    size_t idx16 = (size_t)blockIdx.x * blockDim.x + threadIdx.x;  // 4,194,304 groups of 16
    int o = (int)((idx16 >> 8) & (COUT - 1));                      // 256 groups per (b,o) slab
    float mean = g_sum[o] * (1.0f / NPIX);
    float var  = g_sq[o]  * (1.0f / NPIX) - mean * mean;
    float inv  = rsqrtf(var + 1e-5f);
    float ga = gamma[o] * inv;
    float be = beta[o] - mean * ga;

    const uint4* ysrc = (const uint4*)(g_y + idx16 * 16);
    uint4 p0 = __ldcs(ysrc);
    uint4 p1 = __ldcs(ysrc + 1);
    float4* dst = (float4*)(out + idx16 * 16);

    float2 f;
    float4 o4;
    f = __half22float2(*(__half2*)&p0.x); o4.x = f.x * ga + be; o4.y = f.y * ga + be;
    f = __half22float2(*(__half2*)&p0.y); o4.z = f.x * ga + be; o4.w = f.y * ga + be;
    __stcs(dst + 0, o4);
    f = __half22float2(*(__half2*)&p0.z); o4.x = f.x * ga + be; o4.y = f.y * ga + be;
    f = __half22float2(*(__half2*)&p0.w); o4.z = f.x * ga + be; o4.w = f.y * ga + be;
    __stcs(dst + 1, o4);
    f = __half22float2(*(__half2*)&p1.x); o4.x = f.x * ga + be; o4.y = f.y * ga + be;
    f = __half22float2(*(__half2*)&p1.y); o4.z = f.x * ga + be; o4.w = f.y * ga + be;
    __stcs(dst + 2, o4);
    f = __half22float2(*(__half2*)&p1.z); o4.x = f.x * ga + be; o4.y = f.y * ga + be;
    f = __half22float2(*(__half2*)&p1.w); o4.z = f.x * ga + be; o4.w = f.y * ga + be;
    __stcs(dst + 3, o4);
}

// ============================ launcher ============================
extern "C" void kernel_launch(void* const* d_in, const int* in_sizes, int n_in,
                              void* d_out, int out_size) {
    const float* x     = (const float*)d_in[0];
    const float* w     = (const float*)d_in[1];
    // d_in[2] = conv_b: exactly cancelled by BatchNorm mean subtraction.
    const float* gamma = (const float*)d_in[3];
    const float* beta  = (const float*)d_in[4];
    float* out = (float*)d_out;

    cudaFuncSetAttribute(k_gemm, cudaFuncAttributeMaxDynamicSharedMemorySize, SM_TOTAL);

    k_init<<<4096, 256>>>(w);                 // noise table + fp16 W + zero stats
    k_gemm<<<1024, 256, SM_TOTAL>>>(x);       // fused noise+relu+GEMM+BN-stats, y fp16
    k_norm<<<16384, 256>>>(out, gamma, beta); // finalize BN -> fp32 out (wide)
}

// round 17
// speedup vs baseline: 1.0602x; 1.0077x over previous
#include <cuda_runtime.h>
#include <cuda_fp16.h>
#include <cstdint>

// ============================ problem sizes ============================
#define BB    32
#define CIN   256
#define COUT  512
#define HWSZ  4096                  // 64*64
#define KTOT  256
#define NPIX  131072.0f             // B*H*W per channel

// ============================ device scratch ============================
__device__ __align__(128) float  g_noise[CIN * HWSZ];            // 4 MB
__device__ __align__(128) __half g_w[COUT * KTOT];               // 256 KB  [o][c]
__device__ __align__(128) __half g_y[(size_t)BB * COUT * HWSZ];  // 134 MB
__device__ float g_sum[COUT];
__device__ float g_sq[COUT];
__device__ unsigned g_ctr;                                       // work-steal counter

// ============================ helpers ============================
__device__ __forceinline__ uint32_t smem_u32(const void* p) {
    uint32_t a;
    asm("{ .reg .u64 t; cvta.to.shared.u64 t, %1; cvt.u32.u64 %0, t; }" : "=r"(a) : "l"(p));
    return a;
}
__device__ __forceinline__ void ldsm_x4(uint32_t& r0, uint32_t& r1, uint32_t& r2, uint32_t& r3,
                                        uint32_t addr) {
    asm volatile("ldmatrix.sync.aligned.m8n8.x4.shared.b16 {%0,%1,%2,%3}, [%4];"
                 : "=r"(r0), "=r"(r1), "=r"(r2), "=r"(r3) : "r"(addr));
}
__device__ __forceinline__ void ldsm_x4_t(uint32_t& r0, uint32_t& r1, uint32_t& r2, uint32_t& r3,
                                          uint32_t addr) {
    asm volatile("ldmatrix.sync.aligned.m8n8.x4.trans.shared.b16 {%0,%1,%2,%3}, [%4];"
                 : "=r"(r0), "=r"(r1), "=r"(r2), "=r"(r3) : "r"(addr));
}
__device__ __forceinline__ void mma16816(float* d, const uint32_t* a, uint32_t b0, uint32_t b1) {
    asm volatile("mma.sync.aligned.m16n8k16.row.col.f32.f16.f16.f32 "
                 "{%0,%1,%2,%3}, {%4,%5,%6,%7}, {%8,%9}, {%0,%1,%2,%3};"
                 : "+f"(d[0]), "+f"(d[1]), "+f"(d[2]), "+f"(d[3])
                 : "r"(a[0]), "r"(a[1]), "r"(a[2]), "r"(a[3]), "r"(b0), "r"(b1));
}

// ============================ kernel 0: init ============================
struct LCGTab { unsigned A[21]; unsigned C[21]; };
__host__ __device__ constexpr LCGTab make_tab() {
    LCGTab t{};
    unsigned a = 65539u, c = 1u;
    for (int j = 0; j < 21; j++) {
        t.A[j] = a; t.C[j] = c;
        unsigned c2 = a * c + c;
        a = a * a; c = c2;
    }
    return t;
}
__global__ void k_init(const float* __restrict__ w) {
    constexpr LCGTab T = make_tab();
    int i = blockIdx.x * blockDim.x + threadIdx.x;   // 0 .. 1048575
    unsigned n = (unsigned)i + 1u;
    unsigned rA = 1u, rC = 0u;
    #pragma unroll
    for (int j = 0; j < 21; j++) {
        if ((n >> j) & 1u) { rA = T.A[j] * rA; rC = T.A[j] * rC + T.C[j]; }
    }
    unsigned seed = rA * 12345u + rC;
    g_noise[i] = (float)seed * (float)(0.1 / 4294967295.0);

    if (i < COUT * KTOT) g_w[i] = __float2half_rn(w[i]);
    if (i < COUT) { g_sum[i] = 0.0f; g_sq[i] = 0.0f; }
    if (i == 0) g_ctr = 0u;                           // reset work-steal counter each replay
}

// ============================ kernel 1: fused GEMM (persistent, 2 CTAs/SM) ============================
// Persistent CTA pulls mtiles from g_ctr. Per-mtile: A = relu(x+noise) fp16 full-K in
// smem; B single-buffered per phase from L2; BN-stats + fp16 y epilogue per 128-n tile.
#define SMA_OFF    0                       // [256 k][136 m] half = 69632 B
#define SMB_OFF    69632                   // [128 n][72 k] half = 18432 B
#define STAT_OFF   88064                   // 256 floats = 1024 B
#define CTR_OFF    89088                   // 1 uint
#define SM_TOTAL   89216
#define SMA_STRIDE 136
#define SMB_STRIDE 72
#define NMTILES    1024

__global__ void __launch_bounds__(256, 2) k_gemm(const float* __restrict__ x) {
    extern __shared__ char smem[];
    __half* smA = (__half*)(smem + SMA_OFF);
    __half* smB = (__half*)(smem + SMB_OFF);
    float*  sums = (float*)(smem + STAT_OFF);
    float*  sqs  = sums + 128;
    unsigned* smTile = (unsigned*)(smem + CTR_OFF);
    uint32_t smA_u = smem_u32(smA);
    uint32_t smB_u = smem_u32(smB);

    int tid = threadIdx.x, warp = tid >> 5, lane = tid & 31;
    int mw = (warp >> 2) * 64;         // warp m offset
    int nw = (warp & 3) * 32;          // warp n offset within 128-n tile
    int cl = warp * 8;                 // channels staged per warp per chunk
    int brow = tid & 127, bpart = tid >> 7;
    int g = lane >> 2, t = lane & 3;

    uint32_t aaddr = smA_u + (uint32_t)(((lane & 7) + ((lane >> 4) << 3)) * SMA_STRIDE
                                        + mw + ((lane >> 3) & 1) * 8) * 2u;
    uint32_t blane = smB_u + (uint32_t)((nw + (lane & 7) + ((lane >> 4) << 3)) * SMB_STRIDE
                                        + ((lane >> 3) & 1) * 8) * 2u;

    float acc[16][4];
    #pragma unroll
    for (int i = 0; i < 16; i++)
        #pragma unroll
        for (int j = 0; j < 4; j++) acc[i][j] = 0.0f;

    for (;;) {
        if (tid == 0) *smTile = atomicAdd(&g_ctr, 1u);
        __syncthreads();
        unsigned mtile = *smTile;
        __syncthreads();                   // smTile read before reuse next iter
        if (mtile >= NMTILES) break;

        int b   = (int)(mtile >> 5);
        int hw0 = ((int)mtile & 31) << 7;  // 128-pixel contiguous hw slab

        for (int nt = 0; nt < 4; nt++) {
            for (int kc = 0; kc < 4; kc++) {
                if (nt == 0) {
                    #pragma unroll
                    for (int r = 0; r < 8; r++) {
                        int c = kc * 64 + cl + r;
                        float4 xv = *(const float4*)(x + ((size_t)(b * CIN + c)) * HWSZ + hw0 + lane * 4);
                        float4 nv = *(const float4*)(g_noise + (size_t)c * HWSZ + hw0 + lane * 4);
                        __half2 h01 = __floats2half2_rn(fmaxf(xv.x + nv.x, 0.0f), fmaxf(xv.y + nv.y, 0.0f));
                        __half2 h23 = __floats2half2_rn(fmaxf(xv.z + nv.z, 0.0f), fmaxf(xv.w + nv.w, 0.0f));
                        uint2 pack;
                        pack.x = *(uint32_t*)&h01;
                        pack.y = *(uint32_t*)&h23;
                        *(uint2*)(smA + c * SMA_STRIDE + lane * 4) = pack;
                    }
                }
                {   // B tile for (nt, kc): L2-resident weights
                    const uint4* src = (const uint4*)(g_w + (size_t)(nt * 128 + brow) * KTOT
                                                      + kc * 64 + bpart * 32);
                    uint4* dst = (uint4*)(smB + brow * SMB_STRIDE + bpart * 32);
                    dst[0] = src[0]; dst[1] = src[1]; dst[2] = src[2]; dst[3] = src[3];
                }
                __syncthreads();

                uint32_t abase = aaddr + (uint32_t)(kc * 64 * SMA_STRIDE) * 2u;
                #pragma unroll
                for (int ks = 0; ks < 4; ks++) {
                    uint32_t afr[4][4];
                    #pragma unroll
                    for (int mi = 0; mi < 4; mi++)
                        ldsm_x4_t(afr[mi][0], afr[mi][1], afr[mi][2], afr[mi][3],
                                  abase + (uint32_t)(ks * 16 * SMA_STRIDE + mi * 16) * 2u);
                    uint32_t bfr[2][4];
                    #pragma unroll
                    for (int nip = 0; nip < 2; nip++)
                        ldsm_x4(bfr[nip][0], bfr[nip][1], bfr[nip][2], bfr[nip][3],
                                blane + (uint32_t)(nip * 16 * SMB_STRIDE + ks * 16) * 2u);
                    #pragma unroll
                    for (int mi = 0; mi < 4; mi++)
                        #pragma unroll
                        for (int ni = 0; ni < 4; ni++)
                            mma16816(acc[mi * 4 + ni], afr[mi],
                                     bfr[ni >> 1][(ni & 1) * 2], bfr[ni >> 1][(ni & 1) * 2 + 1]);
                }
                __syncthreads();
            }

            // ---- epilogue for ntile nt: BN stats + y fp16 in two 64-n passes via smB ----
            if (tid < 128) { sums[tid] = 0.0f; sqs[tid] = 0.0f; }

            float lsum[8], lsq[8];
            #pragma unroll
            for (int j = 0; j < 8; j++) { lsum[j] = 0.0f; lsq[j] = 0.0f; }
            #pragma unroll
            for (int mi = 0; mi < 4; mi++)
                #pragma unroll
                for (int ni = 0; ni < 4; ni++) {
                    float c0 = acc[mi * 4 + ni][0], c1 = acc[mi * 4 + ni][1];
                    float c2 = acc[mi * 4 + ni][2], c3 = acc[mi * 4 + ni][3];
                    int j0 = ni * 2;
                    lsum[j0]     += c0 + c2;  lsq[j0]     += c0 * c0 + c2 * c2;
                    lsum[j0 + 1] += c1 + c3;  lsq[j0 + 1] += c1 * c1 + c3 * c3;
                }
            #pragma unroll
            for (int j = 0; j < 8; j++) {
                #pragma unroll
                for (int off = 4; off <= 16; off <<= 1) {
                    lsum[j] += __shfl_xor_sync(0xFFFFFFFFu, lsum[j], off);
                    lsq[j]  += __shfl_xor_sync(0xFFFFFFFFu, lsq[j], off);
                }
            }
            __syncthreads();                  // stat zeroing visible; smB free
            if (g == 0) {
                #pragma unroll
                for (int j = 0; j < 8; j++) {
                    int n = nw + (j >> 1) * 8 + t * 2 + (j & 1);
                    atomicAdd(&sums[n], lsum[j]);
                    atomicAdd(&sqs[n],  lsq[j]);
                }
            }

            __half* smY = smB;                // [64 n][136 m] transpose buffer
            #pragma unroll
            for (int p = 0; p < 2; p++) {
                if ((warp & 2) == p * 2) {
                    int nl = nw - p * 64;     // 0 or 32
                    #pragma unroll
                    for (int mi = 0; mi < 4; mi++)
                        #pragma unroll
                        for (int ni = 0; ni < 4; ni++) {
                            float c0 = acc[mi * 4 + ni][0], c1 = acc[mi * 4 + ni][1];
                            float c2 = acc[mi * 4 + ni][2], c3 = acc[mi * 4 + ni][3];
                            int m0 = mw + mi * 16 + g;
                            int n0 = nl + ni * 8 + t * 2;
                            smY[n0 * SMA_STRIDE + m0]           = __float2half_rn(c0);
                            smY[(n0 + 1) * SMA_STRIDE + m0]     = __float2half_rn(c1);
                            smY[n0 * SMA_STRIDE + m0 + 8]       = __float2half_rn(c2);
                            smY[(n0 + 1) * SMA_STRIDE + m0 + 8] = __float2half_rn(c3);
                        }
                }
                __syncthreads();
                #pragma unroll
                for (int i = 0; i < 8; i++) {
                    int n = warp * 8 + i;
                    uint2 v = *(uint2*)(smY + n * SMA_STRIDE + lane * 4);
                    *(uint2*)(g_y + ((size_t)(b * COUT + nt * 128 + p * 64 + n)) * HWSZ
                              + hw0 + lane * 4) = v;
                }
                __syncthreads();
            }

            if (tid < 128) {
                atomicAdd(&g_sum[nt * 128 + tid], sums[tid]);
                atomicAdd(&g_sq[nt * 128 + tid],  sqs[tid]);
            }
            // reset acc for next ntile / next mtile
            #pragma unroll
            for (int i = 0; i < 16; i++)
                #pragma unroll
                for (int j = 0; j < 4; j++) acc[i][j] = 0.0f;
        }
    }
}

// ============================ kernel 2: BN normalize (wide + reversed) ============================
// 16 elems per thread (one channel): 32B y read + 64B out write; reversed traversal
// starts at y's most-recently-written (L2-resident) end.
__global__ void __launch_bounds__(256) k_norm(float* __restrict__ out,
                                              const float* __restrict__ gamma,
                                              const float* __restrict__ beta) {
    size_t lin   = (size_t)blockIdx.x * blockDim.x + threadIdx.x;  // 4,194,304 threads
    size_t idx16 = (4194304u - 1u) - lin;                          // reversed 16-elem group
    int o = (int)((idx16 >> 8) & (COUT - 1));                      // 256 groups per (b,o) slab
    float mean = g_sum[o] * (1.0f / NPIX);
    float var  = g_sq[o]  * (1.0f / NPIX) - mean * mean;
    float inv  = rsqrtf(var + 1e-5f);
    float ga = gamma[o] * inv;
    float be = beta[o] - mean * ga;

    const uint4* ysrc = (const uint4*)(g_y + idx16 * 16);
    uint4 p0 = __ldcs(ysrc);
    uint4 p1 = __ldcs(ysrc + 1);
    float4* dst = (float4*)(out + idx16 * 16);

    float2 f;
    float4 o4;
    f = __half22float2(*(__half2*)&p0.x); o4.x = f.x * ga + be; o4.y = f.y * ga + be;
    f = __half22float2(*(__half2*)&p0.y); o4.z = f.x * ga + be; o4.w = f.y * ga + be;
    __stcs(dst + 0, o4);
    f = __half22float2(*(__half2*)&p0.z); o4.x = f.x * ga + be; o4.y = f.y * ga + be;
    f = __half22float2(*(__half2*)&p0.w); o4.z = f.x * ga + be; o4.w = f.y * ga + be;
    __stcs(dst + 1, o4);
    f = __half22float2(*(__half2*)&p1.x); o4.x = f.x * ga + be; o4.y = f.y * ga + be;
    f = __half22float2(*(__half2*)&p1.y); o4.z = f.x * ga + be; o4.w = f.y * ga + be;
    __stcs(dst + 2, o4);
    f = __half22float2(*(__half2*)&p1.z); o4.x = f.x * ga + be; o4.y = f.y * ga + be;
    f = __half22float2(*(__half2*)&p1.w); o4.z = f.x * ga + be; o4.w = f.y * ga + be;
    __stcs(dst + 3, o4);
}

// ============================ launcher ============================
extern "C" void kernel_launch(void* const* d_in, const int* in_sizes, int n_in,
                              void* d_out, int out_size) {
    const float* x     = (const float*)d_in[0];
    const float* w     = (const float*)d_in[1];
    // d_in[2] = conv_b: exactly cancelled by BatchNorm mean subtraction.
    const float* gamma = (const float*)d_in[3];
    const float* beta  = (const float*)d_in[4];
    float* out = (float*)d_out;

    cudaFuncSetAttribute(k_gemm, cudaFuncAttributeMaxDynamicSharedMemorySize, SM_TOTAL);

    k_init<<<4096, 256>>>(w);                 // noise table + fp16 W + zero stats + ctr
    k_gemm<<<296, 256, SM_TOTAL>>>(x);        // persistent fused GEMM + BN stats, y fp16
    k_norm<<<16384, 256>>>(out, gamma, beta); // finalize BN -> fp32 out (wide, reversed)
}